// round 12
// baseline (speedup 1.0000x reference)
#include <cuda_runtime.h>
#include <cstdint>

// OffsetPredictor: BOTH layers on mma.sync.m16n8k8.tf32; gelu (tanh.approx) between,
// in D-fragment layout, no shuffles. X(8,2048,256) f32 -> out (8,511,256,2) f32.
//
// Per warp: 16 channels (g, g+8 rowgroups) x NP patches.
// mma1: M=16 ch, K=8 patch rows, N=64 hidden (8 n-tiles), bias in accumulator init.
// mma2: M=16 ch, K=64 hidden (8 k-steps), N=8 (cols 0,1 = outputs, rest zero-weights),
//       A2 fragment == gelu(D1 fragment) under k-permutation folded into B2 weights.
//       DUAL accumulator sets (even/odd k-step) to halve the serial HMMA chain.
// Gelu outputs are fed to mma2 as RAW fp32 bits (HW tf32 truncation) - no cvt.

#define B_DIM   8
#define L_DIM   2048
#define C_DIM   256
#define P_CNT   511
#define HID     64
#define NP      8
#define THREADS 128

__device__ __forceinline__ uint64_t pk2(float lo, float hi) {
    uint64_t r; asm("mov.b64 %0, {%1, %2};" : "=l"(r) : "f"(lo), "f"(hi)); return r;
}
__device__ __forceinline__ void unpk2(uint64_t v, float& lo, float& hi) {
    asm("mov.b64 {%0, %1}, %2;" : "=f"(lo), "=f"(hi) : "l"(v));
}
__device__ __forceinline__ uint64_t fma2(uint64_t a, uint64_t b, uint64_t c) {
    uint64_t d; asm("fma.rn.f32x2 %0, %1, %2, %3;" : "=l"(d) : "l"(a), "l"(b), "l"(c)); return d;
}
__device__ __forceinline__ uint64_t mul2(uint64_t a, uint64_t b) {
    uint64_t d; asm("mul.rn.f32x2 %0, %1, %2;" : "=l"(d) : "l"(a), "l"(b)); return d;
}
__device__ __forceinline__ float tanha(float x) {
    float r; asm("tanh.approx.f32 %0, %1;" : "=f"(r) : "f"(x)); return r;
}
__device__ __forceinline__ uint32_t tf32r(float x) {
    uint32_t r; asm("cvt.rna.tf32.f32 %0, %1;" : "=r"(r) : "f"(x)); return r;
}

__device__ __forceinline__ void mma_tf32(float& c0, float& c1, float& c2, float& c3,
                                         uint32_t a0, uint32_t a1, uint32_t a2, uint32_t a3,
                                         uint32_t b0, uint32_t b1) {
    asm volatile("mma.sync.aligned.m16n8k8.row.col.f32.tf32.tf32.f32 "
        "{%0,%1,%2,%3}, {%4,%5,%6,%7}, {%8,%9}, {%0,%1,%2,%3};"
        : "+f"(c0), "+f"(c1), "+f"(c2), "+f"(c3)
        : "r"(a0), "r"(a1), "r"(a2), "r"(a3), "r"(b0), "r"(b1));
}

// y = x + x*tanh(x*R(x^2));  (W2 prescaled by 0.5 makes this 2*gelu -> exact)
// 3-term R(t) = GT1 + GT3*t + GT5*t^2 fitted so tanh(x*R(x^2)) ~ erf(x/sqrt(2));
// weighted gelu abs err <= ~6e-5 for |x| <= 7; saturation sign-safe to |x| ~ 13.
#define GT1 0.79788456f
#define GT3 0.036497f
#define GT5 (-2.367e-4f)

__device__ __forceinline__ uint64_t gelu2y(uint64_t x2, uint64_t T1, uint64_t T3,
                                           uint64_t T5) {
    uint64_t t2 = mul2(x2, x2);
    uint64_t r  = fma2(T5, t2, T3);
    r = fma2(r, t2, T1);
    uint64_t s2 = mul2(x2, r);
    float sl, sh; unpk2(s2, sl, sh);
    uint64_t tp = pk2(tanha(sl), tanha(sh));
    return fma2(x2, tp, x2);           // x*(1 + tanh(s))
}

__global__ __launch_bounds__(THREADS, 8) void offset_predictor_mma2(
    const float* __restrict__ X,
    const float* __restrict__ W1,   // (64, 8)
    const float* __restrict__ b1,   // (64,)
    const float* __restrict__ W2,   // (2, 64)
    const float* __restrict__ b2,   // (2,)
    float* __restrict__ out)        // (8, 511, 256, 2)
{
    __shared__ float sB1[HID];
    const int tid = threadIdx.x;
    if (tid < HID) sB1[tid] = b1[tid];
    __syncthreads();

    const int lane = tid & 31;
    const int warp = tid >> 5;
    const int g    = lane >> 2;     // 0..7
    const int t    = lane & 3;      // 0..3
    const int b    = blockIdx.z;
    const int c    = blockIdx.y * 64 + warp * 16 + g;   // rowgroup A; rowgroup B = c+8
    const int p0   = blockIdx.x * NP;

    // mma1 B fragments (hidden n-tile nt): b0 = W1[nt*8+g][t], b1 = W1[nt*8+g][t+4]
    uint32_t bf0[8], bf1[8];
    #pragma unroll
    for (int nt = 0; nt < 8; nt++) {
        const int j = nt * 8 + g;
        bf0[nt] = tf32r(W1[j * 8 + t]);
        bf1[nt] = tf32r(W1[j * 8 + t + 4]);
    }

    // mma2 B fragments (k-step kt): k=t holds hidden col 2t of tile kt, k=t+4 holds col 2t+1.
    // Only n=g<2 columns carry W2 (prescaled by 0.5); rest are zero.
    uint32_t c2f0[8], c2f1[8];
    #pragma unroll
    for (int kt = 0; kt < 8; kt++) {
        const int j0 = kt * 8 + 2 * t;
        const float w0 = (g < 2) ? 0.5f * W2[g * HID + j0]     : 0.0f;
        const float w1 = (g < 2) ? 0.5f * W2[g * HID + j0 + 1] : 0.0f;
        c2f0[kt] = tf32r(w0);
        c2f1[kt] = tf32r(w1);
    }

    const float bias20 = b2[0], bias21 = b2[1];
    const uint64_t T1 = pk2(GT1, GT1), T3 = pk2(GT3, GT3), T5 = pk2(GT5, GT5);

    const float* Xb = X + (size_t)b * (L_DIM * C_DIM);

    // A fragments for patch p: a0 = X[4p+t][c], a1 = X[4p+t][c+8],
    //                          a2 = X[4p+t+4][c], a3 = X[4p+t+4][c+8]
    uint32_t a0 = tf32r(Xb[(size_t)(4 * p0 + t) * C_DIM + c]);
    uint32_t a1 = tf32r(Xb[(size_t)(4 * p0 + t) * C_DIM + c + 8]);
    uint32_t a2 = tf32r(Xb[(size_t)(4 * p0 + t + 4) * C_DIM + c]);
    uint32_t a3 = tf32r(Xb[(size_t)(4 * p0 + t + 4) * C_DIM + c + 8]);

    #pragma unroll 1
    for (int it = 0; it < NP; it++) {
        const int p = p0 + it;
        if (p >= P_CNT) break;          // uniform across block
        if (it > 0) {
            a0 = a2; a1 = a3;
            a2 = tf32r(Xb[(size_t)(4 * p + t + 4) * C_DIM + c]);
            a3 = tf32r(Xb[(size_t)(4 * p + t + 4) * C_DIM + c + 8]);
        }

        // Dual out accumulator sets (even nt -> e, odd nt -> f); bias in e only.
        float e0 = (t == 0) ? bias20 : 0.0f;
        float e1 = (t == 0) ? bias21 : 0.0f;
        float e2 = e0, e3 = e1;
        float f0 = 0.0f, f1 = 0.0f, f2 = 0.0f, f3 = 0.0f;

        #pragma unroll
        for (int nt = 0; nt < 8; nt++) {
            // layer-1: D cols (2t, 2t+1) -> bias init b1[nt*8+2t .. +1]
            const float2 bb = *(const float2*)&sB1[nt * 8 + 2 * t];
            float d0 = bb.x, d1 = bb.y, d2 = bb.x, d3 = bb.y;
            mma_tf32(d0, d1, d2, d3, a0, a1, a2, a3, bf0[nt], bf1[nt]);

            // 2*gelu in D layout: rows g (d0,d1), rows g+8 (d2,d3)
            const uint64_t yA = gelu2y(pk2(d0, d1), T1, T3, T5);
            const uint64_t yB = gelu2y(pk2(d2, d3), T1, T3, T5);
            float g0, g1, g2, g3;
            unpk2(yA, g0, g1);          // G[g][2t], G[g][2t+1]
            unpk2(yB, g2, g3);          // G[g+8][2t], G[g+8][2t+1]

            // layer-2 mma: A2 frag = {G[g][2t], G[g+8][2t], G[g][2t+1], G[g+8][2t+1]}
            // raw fp32 bits -> HW tf32 truncation (no cvt)
            if ((nt & 1) == 0) {
                mma_tf32(e0, e1, e2, e3,
                         __float_as_uint(g0), __float_as_uint(g2),
                         __float_as_uint(g1), __float_as_uint(g3),
                         c2f0[nt], c2f1[nt]);
            } else {
                mma_tf32(f0, f1, f2, f3,
                         __float_as_uint(g0), __float_as_uint(g2),
                         __float_as_uint(g1), __float_as_uint(g3),
                         c2f0[nt], c2f1[nt]);
            }
        }

        if (t == 0) {
            float2* opA = (float2*)(out + ((size_t)(b * P_CNT + p) * C_DIM + c) * 2);
            *opA = make_float2(e0 + f0, e1 + f1);
            float2* opB = (float2*)(out + ((size_t)(b * P_CNT + p) * C_DIM + c + 8) * 2);
            *opB = make_float2(e2 + f2, e3 + f3);
        }
    }
}

extern "C" void kernel_launch(void* const* d_in, const int* in_sizes, int n_in,
                              void* d_out, int out_size) {
    const float* X  = (const float*)d_in[0];
    const float* W1 = (const float*)d_in[1];
    const float* b1 = (const float*)d_in[2];
    const float* W2 = (const float*)d_in[3];
    const float* b2 = (const float*)d_in[4];
    float* out = (float*)d_out;

    dim3 grid((P_CNT + NP - 1) / NP, 4, B_DIM);   // (64, 4, 8)
    offset_predictor_mma2<<<grid, THREADS>>>(X, W1, b1, W2, b2, out);
}

// round 14
// speedup vs baseline: 1.1017x; 1.1017x over previous
#include <cuda_runtime.h>
#include <cstdint>

// OffsetPredictor: BOTH layers on mma.sync.m16n8k8.tf32; gelu (tanh.approx) between,
// in D-fragment layout, no shuffles. X(8,2048,256) f32 -> out (8,511,256,2) f32.
//
// Per warp: 16 channels (g, g+8 rowgroups) x NP patches.
// mma1: M=16 ch, K=8 patch rows, N=64 hidden (8 n-tiles), bias in accumulator init.
// mma2: M=16 ch, K=64 hidden (8 k-steps), N=8 (cols 0,1 = outputs, rest zero-weights),
//       A2 fragment == gelu(D1 fragment) under k-permutation folded into B2 weights.
// Gelu: packed-f32x2 polynomial, SCALAR tail (no pack/unpack of tanh results).
// Gelu outputs feed mma2 as RAW fp32 bits (HW tf32 truncation) - no cvt.

#define B_DIM   8
#define L_DIM   2048
#define C_DIM   256
#define P_CNT   511
#define HID     64
#define NP      8
#define THREADS 128

__device__ __forceinline__ uint64_t pk2(float lo, float hi) {
    uint64_t r; asm("mov.b64 %0, {%1, %2};" : "=l"(r) : "f"(lo), "f"(hi)); return r;
}
__device__ __forceinline__ void unpk2(uint64_t v, float& lo, float& hi) {
    asm("mov.b64 {%0, %1}, %2;" : "=f"(lo), "=f"(hi) : "l"(v));
}
__device__ __forceinline__ uint64_t fma2(uint64_t a, uint64_t b, uint64_t c) {
    uint64_t d; asm("fma.rn.f32x2 %0, %1, %2, %3;" : "=l"(d) : "l"(a), "l"(b), "l"(c)); return d;
}
__device__ __forceinline__ uint64_t mul2(uint64_t a, uint64_t b) {
    uint64_t d; asm("mul.rn.f32x2 %0, %1, %2;" : "=l"(d) : "l"(a), "l"(b)); return d;
}
__device__ __forceinline__ float tanha(float x) {
    float r; asm("tanh.approx.f32 %0, %1;" : "=f"(r) : "f"(x)); return r;
}
__device__ __forceinline__ uint32_t tf32r(float x) {
    uint32_t r; asm("cvt.rna.tf32.f32 %0, %1;" : "=r"(r) : "f"(x)); return r;
}

__device__ __forceinline__ void mma_tf32(float& c0, float& c1, float& c2, float& c3,
                                         uint32_t a0, uint32_t a1, uint32_t a2, uint32_t a3,
                                         uint32_t b0, uint32_t b1) {
    asm volatile("mma.sync.aligned.m16n8k8.row.col.f32.tf32.tf32.f32 "
        "{%0,%1,%2,%3}, {%4,%5,%6,%7}, {%8,%9}, {%0,%1,%2,%3};"
        : "+f"(c0), "+f"(c1), "+f"(c2), "+f"(c3)
        : "r"(a0), "r"(a1), "r"(a2), "r"(a3), "r"(b0), "r"(b1));
}

// y = x + x*tanh(x*R(x^2));  (W2 prescaled by 0.5 makes this 2*gelu -> exact)
// 3-term R(t) = GT1 + GT3*t + GT5*t^2 fitted so tanh(x*R(x^2)) ~ erf(x/sqrt(2));
// weighted gelu abs err <= ~6e-5 for |x| <= 7; saturation sign-safe to |x| ~ 13.
#define GT1 0.79788456f
#define GT3 0.036497f
#define GT5 (-2.367e-4f)

// Packed poly, scalar tail: inputs d0,d1 scalar, outputs y0,y1 scalar.
__device__ __forceinline__ void gelu2s(float d0, float d1, float& y0, float& y1,
                                       uint64_t T1, uint64_t T3, uint64_t T5) {
    uint64_t x2 = pk2(d0, d1);
    uint64_t t2 = mul2(x2, x2);
    uint64_t r  = fma2(T5, t2, T3);
    r = fma2(r, t2, T1);
    uint64_t s2 = mul2(x2, r);
    float sl, sh; unpk2(s2, sl, sh);
    y0 = fmaf(d0, tanha(sl), d0);
    y1 = fmaf(d1, tanha(sh), d1);
}

__global__ __launch_bounds__(THREADS, 8) void offset_predictor_mma2(
    const float* __restrict__ X,
    const float* __restrict__ W1,   // (64, 8)
    const float* __restrict__ b1,   // (64,)
    const float* __restrict__ W2,   // (2, 64)
    const float* __restrict__ b2,   // (2,)
    float* __restrict__ out)        // (8, 511, 256, 2)
{
    __shared__ float sB1[HID];
    const int tid = threadIdx.x;
    if (tid < HID) sB1[tid] = b1[tid];
    __syncthreads();

    const int lane = tid & 31;
    const int warp = tid >> 5;
    const int g    = lane >> 2;     // 0..7
    const int t    = lane & 3;      // 0..3
    const int b    = blockIdx.z;
    const int c    = blockIdx.y * 64 + warp * 16 + g;   // rowgroup A; rowgroup B = c+8
    const int p0   = blockIdx.x * NP;

    // mma1 B fragments (hidden n-tile nt): b0 = W1[nt*8+g][t], b1 = W1[nt*8+g][t+4]
    uint32_t bf0[8], bf1[8];
    #pragma unroll
    for (int nt = 0; nt < 8; nt++) {
        const int j = nt * 8 + g;
        bf0[nt] = tf32r(W1[j * 8 + t]);
        bf1[nt] = tf32r(W1[j * 8 + t + 4]);
    }

    // mma2 B fragments (k-step kt): k=t holds hidden col 2t of tile kt, k=t+4 holds col 2t+1.
    // Only n=g<2 columns carry W2 (prescaled by 0.5); rest are zero.
    uint32_t c2f0[8], c2f1[8];
    #pragma unroll
    for (int kt = 0; kt < 8; kt++) {
        const int j0 = kt * 8 + 2 * t;
        const float w0 = (g < 2) ? 0.5f * W2[g * HID + j0]     : 0.0f;
        const float w1 = (g < 2) ? 0.5f * W2[g * HID + j0 + 1] : 0.0f;
        c2f0[kt] = tf32r(w0);
        c2f1[kt] = tf32r(w1);
    }

    const float bias20 = b2[0], bias21 = b2[1];
    const uint64_t T1 = pk2(GT1, GT1), T3 = pk2(GT3, GT3), T5 = pk2(GT5, GT5);

    const float* Xb = X + (size_t)b * (L_DIM * C_DIM);

    // A fragments for patch p: a0 = X[4p+t][c], a1 = X[4p+t][c+8],
    //                          a2 = X[4p+t+4][c], a3 = X[4p+t+4][c+8]
    uint32_t a0 = tf32r(Xb[(size_t)(4 * p0 + t) * C_DIM + c]);
    uint32_t a1 = tf32r(Xb[(size_t)(4 * p0 + t) * C_DIM + c + 8]);
    uint32_t a2 = tf32r(Xb[(size_t)(4 * p0 + t + 4) * C_DIM + c]);
    uint32_t a3 = tf32r(Xb[(size_t)(4 * p0 + t + 4) * C_DIM + c + 8]);

    #pragma unroll 1
    for (int it = 0; it < NP; it++) {
        const int p = p0 + it;
        if (p >= P_CNT) break;          // uniform across block
        if (it > 0) {
            a0 = a2; a1 = a3;
            a2 = tf32r(Xb[(size_t)(4 * p + t + 4) * C_DIM + c]);
            a3 = tf32r(Xb[(size_t)(4 * p + t + 4) * C_DIM + c + 8]);
        }

        // out accumulators (D2): lanes t==0 own cols 0,1 = the two outputs
        float e0 = (t == 0) ? bias20 : 0.0f;
        float e1 = (t == 0) ? bias21 : 0.0f;
        float e2 = e0, e3 = e1;

        #pragma unroll
        for (int nt = 0; nt < 8; nt++) {
            // layer-1: D cols (2t, 2t+1) -> bias init b1[nt*8+2t .. +1]
            const float2 bb = *(const float2*)&sB1[nt * 8 + 2 * t];
            float d0 = bb.x, d1 = bb.y, d2 = bb.x, d3 = bb.y;
            mma_tf32(d0, d1, d2, d3, a0, a1, a2, a3, bf0[nt], bf1[nt]);

            // 2*gelu in D layout (scalar outputs): rows g (d0,d1), rows g+8 (d2,d3)
            float g0, g1, g2, g3;
            gelu2s(d0, d1, g0, g1, T1, T3, T5);   // G[g][2t], G[g][2t+1]
            gelu2s(d2, d3, g2, g3, T1, T3, T5);   // G[g+8][2t], G[g+8][2t+1]

            // layer-2 mma: A2 frag = {G[g][2t], G[g+8][2t], G[g][2t+1], G[g+8][2t+1]}
            // raw fp32 bits -> HW tf32 truncation (no cvt)
            mma_tf32(e0, e1, e2, e3,
                     __float_as_uint(g0), __float_as_uint(g2),
                     __float_as_uint(g1), __float_as_uint(g3),
                     c2f0[nt], c2f1[nt]);
        }

        if (t == 0) {
            float2* opA = (float2*)(out + ((size_t)(b * P_CNT + p) * C_DIM + c) * 2);
            *opA = make_float2(e0, e1);
            float2* opB = (float2*)(out + ((size_t)(b * P_CNT + p) * C_DIM + c + 8) * 2);
            *opB = make_float2(e2, e3);
        }
    }
}

extern "C" void kernel_launch(void* const* d_in, const int* in_sizes, int n_in,
                              void* d_out, int out_size) {
    const float* X  = (const float*)d_in[0];
    const float* W1 = (const float*)d_in[1];
    const float* b1 = (const float*)d_in[2];
    const float* W2 = (const float*)d_in[3];
    const float* b2 = (const float*)d_in[4];
    float* out = (float*)d_out;

    dim3 grid((P_CNT + NP - 1) / NP, 4, B_DIM);   // (64, 4, 8)
    offset_predictor_mma2<<<grid, THREADS>>>(X, W1, b1, W2, b2, out);
}